// round 2
// baseline (speedup 1.0000x reference)
#include <cuda_runtime.h>
#include <math.h>

// Problem constants
#define B   16
#define N   1024
#define H   256
#define DS  3
#define HEADS 8
#define DH  32
#define TWO_H 512
#define M_ROWS (B * N)          // 16384
#define EPS 1e-5f
#define SCALE 0.17677669529663687f  // 1/sqrt(32)

// ---------------- scratch (static device globals; no allocation) -------------
__device__ float g_f  [M_ROWS * TWO_H];   // layernormed concat   [16384, 512]
__device__ float g_q  [M_ROWS * H];       // [B,N,HEADS,DH] = [16384, 256]
__device__ float g_k  [M_ROWS * H];
__device__ float g_v  [M_ROWS * H];
__device__ float g_msg[M_ROWS * H];       // attention output
__device__ float g_m  [M_ROWS * H];       // msg @ Wo

// ---------------- kernel 1: dual LayerNorm + concat --------------------------
__global__ void ln_concat_kernel(const float* __restrict__ xs,
                                 const float* __restrict__ xo,
                                 const float* __restrict__ gs,
                                 const float* __restrict__ bs,
                                 const float* __restrict__ go,
                                 const float* __restrict__ bo) {
    __shared__ float red[H];
    int row = blockIdx.x;
    int t = threadIdx.x;

    float v1 = xs[row * H + t];
    float v2 = xo[row * H + t];

    // --- norm 1 ---
    red[t] = v1; __syncthreads();
    #pragma unroll
    for (int s = H / 2; s > 0; s >>= 1) {
        if (t < s) red[t] += red[t + s];
        __syncthreads();
    }
    float mean1 = red[0] * (1.0f / H);
    __syncthreads();
    float d1 = v1 - mean1;
    red[t] = d1 * d1; __syncthreads();
    #pragma unroll
    for (int s = H / 2; s > 0; s >>= 1) {
        if (t < s) red[t] += red[t + s];
        __syncthreads();
    }
    float var1 = red[0] * (1.0f / H);
    __syncthreads();
    g_f[row * TWO_H + t] = d1 * rsqrtf(var1 + EPS) * gs[t] + bs[t];

    // --- norm 2 ---
    red[t] = v2; __syncthreads();
    #pragma unroll
    for (int s = H / 2; s > 0; s >>= 1) {
        if (t < s) red[t] += red[t + s];
        __syncthreads();
    }
    float mean2 = red[0] * (1.0f / H);
    __syncthreads();
    float d2 = v2 - mean2;
    red[t] = d2 * d2; __syncthreads();
    #pragma unroll
    for (int s = H / 2; s > 0; s >>= 1) {
        if (t < s) red[t] += red[t + s];
        __syncthreads();
    }
    float var2 = red[0] * (1.0f / H);
    g_f[row * TWO_H + H + t] = d2 * rsqrtf(var2 + EPS) * go[t] + bo[t];
}

// ---------------- kernel 2/4: tiled fp32 GEMM  C[M,256] = A[M,K] * W[K,256] --
// 64x64 tile, BK=16, 256 threads, 4x4 microtile per thread
__global__ void gemm_kernel(const float* __restrict__ A,
                            const float* __restrict__ W,
                            float* __restrict__ C,
                            int K) {
    __shared__ float As[16][64];
    __shared__ float Bs[16][64];

    int tid = threadIdx.x;
    int tx = tid & 15;        // 0..15 -> 4 cols each
    int ty = tid >> 4;        // 0..15 -> 4 rows each
    int row0 = blockIdx.x * 64;
    int col0 = blockIdx.y * 64;

    float acc[4][4];
    #pragma unroll
    for (int i = 0; i < 4; i++)
        #pragma unroll
        for (int j = 0; j < 4; j++) acc[i][j] = 0.0f;

    int a_m  = tid >> 2;            // 0..63
    int a_k4 = (tid & 3) * 4;       // 0,4,8,12
    int b_k  = tid >> 4;            // 0..15
    int b_n4 = (tid & 15) * 4;      // 0..60

    for (int k0 = 0; k0 < K; k0 += 16) {
        float4 a = *(const float4*)&A[(size_t)(row0 + a_m) * K + k0 + a_k4];
        As[a_k4 + 0][a_m] = a.x;
        As[a_k4 + 1][a_m] = a.y;
        As[a_k4 + 2][a_m] = a.z;
        As[a_k4 + 3][a_m] = a.w;

        float4 b = *(const float4*)&W[(size_t)(k0 + b_k) * H + col0 + b_n4];
        *(float4*)&Bs[b_k][b_n4] = b;
        __syncthreads();

        #pragma unroll
        for (int kk = 0; kk < 16; kk++) {
            float4 av = *(float4*)&As[kk][ty * 4];
            float4 bv = *(float4*)&Bs[kk][tx * 4];
            float ar[4] = {av.x, av.y, av.z, av.w};
            float br[4] = {bv.x, bv.y, bv.z, bv.w};
            #pragma unroll
            for (int i = 0; i < 4; i++)
                #pragma unroll
                for (int j = 0; j < 4; j++)
                    acc[i][j] += ar[i] * br[j];
        }
        __syncthreads();
    }

    #pragma unroll
    for (int i = 0; i < 4; i++) {
        float4 v = make_float4(acc[i][0], acc[i][1], acc[i][2], acc[i][3]);
        *(float4*)&C[(size_t)(row0 + ty * 4 + i) * H + col0 + tx * 4] = v;
    }
}

// ---------------- kernel 3: flash attention ----------------------------------
// grid (N/64, HEADS, B), 64 threads; one q row per thread.
__global__ void attn_kernel() {
    __shared__ float Ks[64][32];
    __shared__ float Vs[64][32];

    int b = blockIdx.z;
    int h = blockIdx.y;
    int q0 = blockIdx.x * 64;
    int t = threadIdx.x;

    // load q row (scaled)
    float qr[DH];
    const float* qp = g_q + ((size_t)(b * N + q0 + t) * HEADS + h) * DH;
    #pragma unroll
    for (int d = 0; d < DH; d += 4) {
        float4 v = *(const float4*)&qp[d];
        qr[d + 0] = v.x * SCALE; qr[d + 1] = v.y * SCALE;
        qr[d + 2] = v.z * SCALE; qr[d + 3] = v.w * SCALE;
    }

    float mmax = -INFINITY, l = 0.0f;
    float o[DH];
    #pragma unroll
    for (int d = 0; d < DH; d++) o[d] = 0.0f;

    for (int j0 = 0; j0 < N; j0 += 64) {
        // cooperative tile load: 512 float4s, 8 per thread
        #pragma unroll
        for (int it = 0; it < 8; it++) {
            int fi = it * 64 + t;
            int j  = fi >> 3;
            int d4 = (fi & 7) * 4;
            const float* kp = g_k + ((size_t)(b * N + j0 + j) * HEADS + h) * DH + d4;
            const float* vp = g_v + ((size_t)(b * N + j0 + j) * HEADS + h) * DH + d4;
            *(float4*)&Ks[j][d4] = *(const float4*)kp;
            *(float4*)&Vs[j][d4] = *(const float4*)vp;
        }
        __syncthreads();

        #pragma unroll 4
        for (int j = 0; j < 64; j++) {
            float s = 0.0f;
            #pragma unroll
            for (int d = 0; d < DH; d += 4) {
                float4 kv = *(float4*)&Ks[j][d];
                s += qr[d + 0] * kv.x + qr[d + 1] * kv.y
                   + qr[d + 2] * kv.z + qr[d + 3] * kv.w;
            }
            if (s > mmax) {
                float c = __expf(mmax - s);
                mmax = s;
                l *= c;
                #pragma unroll
                for (int d = 0; d < DH; d++) o[d] *= c;
            }
            float p = __expf(s - mmax);
            l += p;
            #pragma unroll
            for (int d = 0; d < DH; d += 4) {
                float4 vv = *(float4*)&Vs[j][d];
                o[d + 0] += p * vv.x; o[d + 1] += p * vv.y;
                o[d + 2] += p * vv.z; o[d + 3] += p * vv.w;
            }
        }
        __syncthreads();
    }

    float inv = 1.0f / l;
    float* op = g_msg + (size_t)(b * N + q0 + t) * H + h * DH;
    #pragma unroll
    for (int d = 0; d < DH; d += 4) {
        float4 v = make_float4(o[d] * inv, o[d + 1] * inv, o[d + 2] * inv, o[d + 3] * inv);
        *(float4*)&op[d] = v;
    }
}

// ---------------- kernel 5: residual + position head -------------------------
// 256 threads = 8 warps; warp w handles row blockIdx.x*8 + w
__global__ void finish_kernel(const float* __restrict__ x_out,
                              const float* __restrict__ Wp,
                              float* __restrict__ out_x,
                              float* __restrict__ out_p) {
    int warp = threadIdx.x >> 5;
    int lane = threadIdx.x & 31;
    int row = blockIdx.x * 8 + warp;

    const float* mr = g_m + (size_t)row * H;
    float p0 = 0.0f, p1 = 0.0f, p2 = 0.0f;
    #pragma unroll
    for (int c = lane; c < H; c += 32) {
        float mv = mr[c];
        out_x[(size_t)row * H + c] = x_out[(size_t)row * H + c] + mv;
        p0 += mv * Wp[c * DS + 0];
        p1 += mv * Wp[c * DS + 1];
        p2 += mv * Wp[c * DS + 2];
    }
    #pragma unroll
    for (int off = 16; off > 0; off >>= 1) {
        p0 += __shfl_xor_sync(0xFFFFFFFF, p0, off);
        p1 += __shfl_xor_sync(0xFFFFFFFF, p1, off);
        p2 += __shfl_xor_sync(0xFFFFFFFF, p2, off);
    }
    if (lane == 0) {
        out_p[(size_t)row * DS + 0] = p0;
        out_p[(size_t)row * DS + 1] = p1;
        out_p[(size_t)row * DS + 2] = p2;
    }
}

// ---------------- launcher ----------------------------------------------------
extern "C" void kernel_launch(void* const* d_in, const int* in_sizes, int n_in,
                              void* d_out, int out_size) {
    const float* x_source = (const float*)d_in[0];
    // d_in[1] = p_source (unused)
    const float* x_out    = (const float*)d_in[2];
    // d_in[3] = p_out (unused)
    const float* gs = (const float*)d_in[4];
    const float* bs = (const float*)d_in[5];
    const float* go = (const float*)d_in[6];
    const float* bo = (const float*)d_in[7];
    const float* Wq = (const float*)d_in[8];
    const float* Wk = (const float*)d_in[9];
    const float* Wv = (const float*)d_in[10];
    const float* Wo = (const float*)d_in[11];
    const float* Wp = (const float*)d_in[12];

    float* out   = (float*)d_out;
    float* out_x = out;                       // [16384, 256]
    float* out_p = out + (size_t)M_ROWS * H;  // [16384, 3]

    // resolve device scratch symbols (no allocation; symbol addresses)
    float *pf, *pq, *pk, *pv, *pmsg, *pm;
    cudaGetSymbolAddress((void**)&pf,   g_f);
    cudaGetSymbolAddress((void**)&pq,   g_q);
    cudaGetSymbolAddress((void**)&pk,   g_k);
    cudaGetSymbolAddress((void**)&pv,   g_v);
    cudaGetSymbolAddress((void**)&pmsg, g_msg);
    cudaGetSymbolAddress((void**)&pm,   g_m);

    // 1) layernorm + concat
    ln_concat_kernel<<<M_ROWS, H>>>(x_source, x_out, gs, bs, go, bo);

    // 2) QKV projections: [16384,512] @ [512,256]
    dim3 ggrid(M_ROWS / 64, H / 64);
    gemm_kernel<<<ggrid, 256>>>(pf, Wq, pq, TWO_H);
    gemm_kernel<<<ggrid, 256>>>(pf, Wk, pk, TWO_H);
    gemm_kernel<<<ggrid, 256>>>(pf, Wv, pv, TWO_H);

    // 3) attention
    dim3 agrid(N / 64, HEADS, B);
    attn_kernel<<<agrid, 64>>>();

    // 4) output projection: [16384,256] @ [256,256]
    gemm_kernel<<<ggrid, 256>>>(pmsg, Wo, pm, H);

    // 5) residual + position head
    finish_kernel<<<M_ROWS / 8, 256>>>(x_out, Wp, out_x, out_p);
}

// round 4
// speedup vs baseline: 1.1105x; 1.1105x over previous
#include <cuda_runtime.h>
#include <math.h>

// Problem constants
#define B   16
#define N   1024
#define H   256
#define DS  3
#define HEADS 8
#define DH  32
#define TWO_H 512
#define M_ROWS (B * N)          // 16384
#define EPS 1e-5f
#define SCALE 0.17677669529663687f  // 1/sqrt(32)

// GEMM tiling
#define BM 128
#define BN 64
#define BK 16

// ---------------- scratch (static device globals; no allocation) -------------
__device__ float g_f  [M_ROWS * TWO_H];   // layernormed concat   [16384, 512]
__device__ float g_q  [M_ROWS * H];       // [B,N,HEADS,DH]
__device__ float g_k  [M_ROWS * H];
__device__ float g_v  [M_ROWS * H];
__device__ float g_msg[M_ROWS * H];       // attention output
__device__ float g_m  [M_ROWS * H];       // msg @ Wo

// ---------------- kernel 1: dual LayerNorm + concat (one-pass, shfl) ---------
__global__ void ln_concat_kernel(const float* __restrict__ xs,
                                 const float* __restrict__ xo,
                                 const float* __restrict__ gs,
                                 const float* __restrict__ bs,
                                 const float* __restrict__ go,
                                 const float* __restrict__ bo) {
    __shared__ float red[8][4];
    __shared__ float res[4];
    int row = blockIdx.x;
    int t = threadIdx.x;
    int lane = t & 31, warp = t >> 5;

    float v1 = xs[row * H + t];
    float v2 = xo[row * H + t];

    float s1 = v1, q1 = v1 * v1, s2 = v2, q2 = v2 * v2;
    #pragma unroll
    for (int off = 16; off > 0; off >>= 1) {
        s1 += __shfl_xor_sync(0xFFFFFFFFu, s1, off);
        q1 += __shfl_xor_sync(0xFFFFFFFFu, q1, off);
        s2 += __shfl_xor_sync(0xFFFFFFFFu, s2, off);
        q2 += __shfl_xor_sync(0xFFFFFFFFu, q2, off);
    }
    if (lane == 0) {
        red[warp][0] = s1; red[warp][1] = q1;
        red[warp][2] = s2; red[warp][3] = q2;
    }
    __syncthreads();
    if (t < 32) {
        int q = t >> 3, w = t & 7;
        float x = red[w][q];
        x += __shfl_xor_sync(0xFFFFFFFFu, x, 1);
        x += __shfl_xor_sync(0xFFFFFFFFu, x, 2);
        x += __shfl_xor_sync(0xFFFFFFFFu, x, 4);
        if (w == 0) res[q] = x;
    }
    __syncthreads();

    float mean1 = res[0] * (1.0f / H);
    float var1  = res[1] * (1.0f / H) - mean1 * mean1;
    float mean2 = res[2] * (1.0f / H);
    float var2  = res[3] * (1.0f / H) - mean2 * mean2;

    g_f[row * TWO_H + t]     = (v1 - mean1) * rsqrtf(var1 + EPS) * gs[t] + bs[t];
    g_f[row * TWO_H + H + t] = (v2 - mean2) * rsqrtf(var2 + EPS) * go[t] + bo[t];
}

// ---------------- GEMM body: C[BMxBN] tile = A[M,K] * W[K,256] ----------------
// 256 threads, 8x4 microtile per thread
__device__ __forceinline__ void gemm_body(const float* __restrict__ A,
                                          const float* __restrict__ W,
                                          float* __restrict__ C,
                                          int K, int row0, int col0) {
    __shared__ float As[BK][BM];
    __shared__ float Bs[BK][BN];

    int tid = threadIdx.x;
    int tx = tid & 15;        // 0..15 -> 4 cols
    int ty = tid >> 4;        // 0..15 -> 8 rows

    float acc[8][4];
    #pragma unroll
    for (int i = 0; i < 8; i++)
        #pragma unroll
        for (int j = 0; j < 4; j++) acc[i][j] = 0.0f;

    int a_m = tid >> 1;           // 0..127
    int a_k = (tid & 1) * 8;      // 0 or 8
    int b_k = tid >> 4;           // 0..15
    int b_n = (tid & 15) * 4;     // 0..60

    for (int k0 = 0; k0 < K; k0 += BK) {
        const float* ap = A + (size_t)(row0 + a_m) * K + k0 + a_k;
        float4 a0 = *(const float4*)ap;
        float4 a1 = *(const float4*)(ap + 4);
        As[a_k + 0][a_m] = a0.x; As[a_k + 1][a_m] = a0.y;
        As[a_k + 2][a_m] = a0.z; As[a_k + 3][a_m] = a0.w;
        As[a_k + 4][a_m] = a1.x; As[a_k + 5][a_m] = a1.y;
        As[a_k + 6][a_m] = a1.z; As[a_k + 7][a_m] = a1.w;

        *(float4*)&Bs[b_k][b_n] = *(const float4*)&W[(size_t)(k0 + b_k) * H + col0 + b_n];
        __syncthreads();

        #pragma unroll
        for (int kk = 0; kk < BK; kk++) {
            float ar[8];
            *(float4*)&ar[0] = *(float4*)&As[kk][ty * 8];
            *(float4*)&ar[4] = *(float4*)&As[kk][ty * 8 + 4];
            float4 bv = *(float4*)&Bs[kk][tx * 4];
            float br[4] = {bv.x, bv.y, bv.z, bv.w};
            #pragma unroll
            for (int i = 0; i < 8; i++)
                #pragma unroll
                for (int j = 0; j < 4; j++)
                    acc[i][j] += ar[i] * br[j];
        }
        __syncthreads();
    }

    #pragma unroll
    for (int i = 0; i < 8; i++) {
        float4 v = make_float4(acc[i][0], acc[i][1], acc[i][2], acc[i][3]);
        *(float4*)&C[(size_t)(row0 + ty * 8 + i) * H + col0 + tx * 4] = v;
    }
}

// fused QKV: grid (M/BM, 12); y/4 selects W & C, y%4 selects 64-col block
__global__ void __launch_bounds__(256)
qkv_gemm_kernel(const float* __restrict__ Wq,
                const float* __restrict__ Wk,
                const float* __restrict__ Wv) {
    int sel = blockIdx.y >> 2;
    const float* W = (sel == 0) ? Wq : (sel == 1) ? Wk : Wv;
    float* C = (sel == 0) ? g_q : (sel == 1) ? g_k : g_v;
    gemm_body(g_f, W, C, TWO_H, blockIdx.x * BM, (blockIdx.y & 3) * BN);
}

// output projection: grid (M/BM, 4)
__global__ void __launch_bounds__(256)
wo_gemm_kernel(const float* __restrict__ Wo) {
    gemm_body(g_msg, Wo, g_m, H, blockIdx.x * BM, blockIdx.y * BN);
}

// ---------------- attention: grid (N/128, HEADS, B), 128 threads --------------
// one q row per thread; no max-tracking (scores are O(1), exp is safe & exact
// softmax is invariant to the max shift)
__global__ void __launch_bounds__(128)
attn_kernel() {
    __shared__ float Ks[64][32];
    __shared__ float Vs[64][32];

    int b = blockIdx.z;
    int h = blockIdx.y;
    int q0 = blockIdx.x * 128;
    int t = threadIdx.x;

    float qr[DH];
    const float* qp = g_q + ((size_t)(b * N + q0 + t) * HEADS + h) * DH;
    #pragma unroll
    for (int d = 0; d < DH; d += 4) {
        float4 v = *(const float4*)&qp[d];
        qr[d + 0] = v.x * SCALE; qr[d + 1] = v.y * SCALE;
        qr[d + 2] = v.z * SCALE; qr[d + 3] = v.w * SCALE;
    }

    float l = 0.0f;
    float o[DH];
    #pragma unroll
    for (int d = 0; d < DH; d++) o[d] = 0.0f;

    for (int j0 = 0; j0 < N; j0 += 64) {
        // cooperative K/V tile load: 512 float4 each, 4 per thread
        #pragma unroll
        for (int it = 0; it < 4; it++) {
            int fi = it * 128 + t;
            int j  = fi >> 3;
            int d4 = (fi & 7) * 4;
            size_t base = ((size_t)(b * N + j0 + j) * HEADS + h) * DH + d4;
            *(float4*)&Ks[j][d4] = *(const float4*)&g_k[base];
            *(float4*)&Vs[j][d4] = *(const float4*)&g_v[base];
        }
        __syncthreads();

        #pragma unroll 4
        for (int j = 0; j < 64; j++) {
            float s = 0.0f;
            #pragma unroll
            for (int d = 0; d < DH; d += 4) {
                float4 kv = *(float4*)&Ks[j][d];
                s += qr[d + 0] * kv.x + qr[d + 1] * kv.y
                   + qr[d + 2] * kv.z + qr[d + 3] * kv.w;
            }
            float p = __expf(s);
            l += p;
            #pragma unroll
            for (int d = 0; d < DH; d += 4) {
                float4 vv = *(float4*)&Vs[j][d];
                o[d + 0] += p * vv.x; o[d + 1] += p * vv.y;
                o[d + 2] += p * vv.z; o[d + 3] += p * vv.w;
            }
        }
        __syncthreads();
    }

    float inv = 1.0f / l;
    float* op = g_msg + (size_t)(b * N + q0 + t) * H + h * DH;
    #pragma unroll
    for (int d = 0; d < DH; d += 4) {
        float4 v = make_float4(o[d] * inv, o[d + 1] * inv, o[d + 2] * inv, o[d + 3] * inv);
        *(float4*)&op[d] = v;
    }
}

// ---------------- kernel 5: residual + position head -------------------------
__global__ void finish_kernel(const float* __restrict__ x_out,
                              const float* __restrict__ Wp,
                              float* __restrict__ out_x,
                              float* __restrict__ out_p) {
    int warp = threadIdx.x >> 5;
    int lane = threadIdx.x & 31;
    int row = blockIdx.x * 8 + warp;

    const float* mr = g_m + (size_t)row * H;
    float p0 = 0.0f, p1 = 0.0f, p2 = 0.0f;
    #pragma unroll
    for (int c = lane; c < H; c += 32) {
        float mv = mr[c];
        out_x[(size_t)row * H + c] = x_out[(size_t)row * H + c] + mv;
        p0 += mv * Wp[c * DS + 0];
        p1 += mv * Wp[c * DS + 1];
        p2 += mv * Wp[c * DS + 2];
    }
    #pragma unroll
    for (int off = 16; off > 0; off >>= 1) {
        p0 += __shfl_xor_sync(0xFFFFFFFF, p0, off);
        p1 += __shfl_xor_sync(0xFFFFFFFF, p1, off);
        p2 += __shfl_xor_sync(0xFFFFFFFF, p2, off);
    }
    if (lane == 0) {
        out_p[(size_t)row * DS + 0] = p0;
        out_p[(size_t)row * DS + 1] = p1;
        out_p[(size_t)row * DS + 2] = p2;
    }
}

// ---------------- launcher ----------------------------------------------------
extern "C" void kernel_launch(void* const* d_in, const int* in_sizes, int n_in,
                              void* d_out, int out_size) {
    const float* x_source = (const float*)d_in[0];
    const float* x_out    = (const float*)d_in[2];
    const float* gs = (const float*)d_in[4];
    const float* bs = (const float*)d_in[5];
    const float* go = (const float*)d_in[6];
    const float* bo = (const float*)d_in[7];
    const float* Wq = (const float*)d_in[8];
    const float* Wk = (const float*)d_in[9];
    const float* Wv = (const float*)d_in[10];
    const float* Wo = (const float*)d_in[11];
    const float* Wp = (const float*)d_in[12];

    float* out   = (float*)d_out;
    float* out_x = out;
    float* out_p = out + (size_t)M_ROWS * H;

    // 1) layernorm + concat
    ln_concat_kernel<<<M_ROWS, H>>>(x_source, x_out, gs, bs, go, bo);

    // 2) fused QKV projections: [16384,512] @ [512,256] x3
    dim3 qkv_grid(M_ROWS / BM, 12);
    qkv_gemm_kernel<<<qkv_grid, 256>>>(Wq, Wk, Wv);

    // 3) attention
    dim3 agrid(N / 128, HEADS, B);
    attn_kernel<<<agrid, 128>>>();

    // 4) output projection
    dim3 wo_grid(M_ROWS / BM, 4);
    wo_gemm_kernel<<<wo_grid, 256>>>(Wo);

    // 5) residual + position head
    finish_kernel<<<M_ROWS / 8, 256>>>(x_out, Wp, out_x, out_p);
}

// round 7
// speedup vs baseline: 3.0546x; 2.7508x over previous
#include <cuda_runtime.h>
#include <math.h>
#include <stdint.h>

// Problem constants
#define B   16
#define N   1024
#define H   256
#define DS  3
#define HEADS 8
#define DH  32
#define TWO_H 512
#define M_ROWS (B * N)          // 16384
#define EPS 1e-5f
#define SCALE 0.17677669529663687f  // 1/sqrt(32)

// ---------------- scratch (static device globals; no allocation) -------------
__device__ float g_f  [M_ROWS * TWO_H];   // layernormed concat [16384, 512]
__device__ float g_q  [M_ROWS * H];
__device__ float g_k  [M_ROWS * H];
__device__ float g_v  [M_ROWS * H];
__device__ float g_msg[M_ROWS * H];
__device__ float g_m  [M_ROWS * H];

// ---------------- tf32 helpers ------------------------------------------------
__device__ __forceinline__ uint32_t f2tf32(float f) {
    uint32_t u;
    asm("cvt.rna.tf32.f32 %0, %1;" : "=r"(u) : "f"(f));
    return u;
}

__device__ __forceinline__ void mma_tf32(float& c0, float& c1, float& c2, float& c3,
                                         uint32_t a0, uint32_t a1, uint32_t a2, uint32_t a3,
                                         uint32_t b0, uint32_t b1) {
    asm volatile(
        "mma.sync.aligned.m16n8k8.row.col.f32.tf32.tf32.f32 "
        "{%0,%1,%2,%3}, {%4,%5,%6,%7}, {%8,%9}, {%0,%1,%2,%3};\n"
        : "+f"(c0), "+f"(c1), "+f"(c2), "+f"(c3)
        : "r"(a0), "r"(a1), "r"(a2), "r"(a3), "r"(b0), "r"(b1));
}

// ---------------- kernel 1: dual LayerNorm + concat (one-pass, shfl) ---------
__global__ void ln_concat_kernel(const float* __restrict__ xs,
                                 const float* __restrict__ xo,
                                 const float* __restrict__ gs,
                                 const float* __restrict__ bs,
                                 const float* __restrict__ go,
                                 const float* __restrict__ bo) {
    __shared__ float red[8][4];
    __shared__ float res[4];
    int row = blockIdx.x;
    int t = threadIdx.x;
    int lane = t & 31, warp = t >> 5;

    float v1 = xs[row * H + t];
    float v2 = xo[row * H + t];

    float s1 = v1, q1 = v1 * v1, s2 = v2, q2 = v2 * v2;
    #pragma unroll
    for (int off = 16; off > 0; off >>= 1) {
        s1 += __shfl_xor_sync(0xFFFFFFFFu, s1, off);
        q1 += __shfl_xor_sync(0xFFFFFFFFu, q1, off);
        s2 += __shfl_xor_sync(0xFFFFFFFFu, s2, off);
        q2 += __shfl_xor_sync(0xFFFFFFFFu, q2, off);
    }
    if (lane == 0) {
        red[warp][0] = s1; red[warp][1] = q1;
        red[warp][2] = s2; red[warp][3] = q2;
    }
    __syncthreads();
    if (t < 32) {
        int q = t >> 3, w = t & 7;
        float x = red[w][q];
        x += __shfl_xor_sync(0xFFFFFFFFu, x, 1);
        x += __shfl_xor_sync(0xFFFFFFFFu, x, 2);
        x += __shfl_xor_sync(0xFFFFFFFFu, x, 4);
        if (w == 0) res[q] = x;
    }
    __syncthreads();

    float mean1 = res[0] * (1.0f / H);
    float var1  = res[1] * (1.0f / H) - mean1 * mean1;
    float mean2 = res[2] * (1.0f / H);
    float var2  = res[3] * (1.0f / H) - mean2 * mean2;

    g_f[row * TWO_H + t]     = (v1 - mean1) * rsqrtf(var1 + EPS) * gs[t] + bs[t];
    g_f[row * TWO_H + H + t] = (v2 - mean2) * rsqrtf(var2 + EPS) * go[t] + bo[t];
}

// ---------------- tf32 MMA GEMM: C[M,256] = A[M,K] @ W[K,256] ----------------
// 128x64 block tile, 8 warps (4 m x 2 n), each warp 32x32, BK=32
__device__ __forceinline__ void gemm_mma_body(const float* __restrict__ A,
                                              const float* __restrict__ W,
                                              float* __restrict__ C,
                                              int K, int row0, int col0) {
    __shared__ uint32_t As[128][36];   // row-major A tile (tf32)
    __shared__ uint32_t Bs[32][72];    // [k][n] tile (tf32)

    int t = threadIdx.x;
    int w = t >> 5, lane = t & 31;
    int quad = lane >> 2, c = lane & 3;
    int wm = (w & 3) * 32;   // warp m offset
    int wn = (w >> 2) * 32;  // warp n offset

    float acc[2][4][4];
    #pragma unroll
    for (int mt = 0; mt < 2; mt++)
        #pragma unroll
        for (int nt = 0; nt < 4; nt++)
            #pragma unroll
            for (int i = 0; i < 4; i++) acc[mt][nt][i] = 0.0f;

    int a_row = t >> 1, a_col = (t & 1) * 16;
    int b_row = t >> 3, b_col = (t & 7) * 8;

    for (int k0 = 0; k0 < K; k0 += 32) {
        // load A tile 128x32
        const float* ap = A + (size_t)(row0 + a_row) * K + k0 + a_col;
        float4 f0 = *(const float4*)(ap + 0);
        float4 f1 = *(const float4*)(ap + 4);
        float4 f2 = *(const float4*)(ap + 8);
        float4 f3 = *(const float4*)(ap + 12);
        uint4 u;
        u.x = f2tf32(f0.x); u.y = f2tf32(f0.y); u.z = f2tf32(f0.z); u.w = f2tf32(f0.w);
        *(uint4*)&As[a_row][a_col + 0] = u;
        u.x = f2tf32(f1.x); u.y = f2tf32(f1.y); u.z = f2tf32(f1.z); u.w = f2tf32(f1.w);
        *(uint4*)&As[a_row][a_col + 4] = u;
        u.x = f2tf32(f2.x); u.y = f2tf32(f2.y); u.z = f2tf32(f2.z); u.w = f2tf32(f2.w);
        *(uint4*)&As[a_row][a_col + 8] = u;
        u.x = f2tf32(f3.x); u.y = f2tf32(f3.y); u.z = f2tf32(f3.z); u.w = f2tf32(f3.w);
        *(uint4*)&As[a_row][a_col + 12] = u;

        // load B tile 32x64
        const float* bp = W + (size_t)(k0 + b_row) * H + col0 + b_col;
        float4 g0 = *(const float4*)(bp + 0);
        float4 g1 = *(const float4*)(bp + 4);
        u.x = f2tf32(g0.x); u.y = f2tf32(g0.y); u.z = f2tf32(g0.z); u.w = f2tf32(g0.w);
        *(uint4*)&Bs[b_row][b_col + 0] = u;
        u.x = f2tf32(g1.x); u.y = f2tf32(g1.y); u.z = f2tf32(g1.z); u.w = f2tf32(g1.w);
        *(uint4*)&Bs[b_row][b_col + 4] = u;
        __syncthreads();

        #pragma unroll
        for (int ks = 0; ks < 4; ks++) {
            int kk = ks * 8;
            uint32_t a[2][4];
            #pragma unroll
            for (int mt = 0; mt < 2; mt++) {
                int mrow = wm + mt * 16;
                a[mt][0] = As[mrow + quad][kk + c];
                a[mt][1] = As[mrow + quad + 8][kk + c];
                a[mt][2] = As[mrow + quad][kk + c + 4];
                a[mt][3] = As[mrow + quad + 8][kk + c + 4];
            }
            #pragma unroll
            for (int nt = 0; nt < 4; nt++) {
                uint32_t b0 = Bs[kk + c][wn + nt * 8 + quad];
                uint32_t b1 = Bs[kk + c + 4][wn + nt * 8 + quad];
                #pragma unroll
                for (int mt = 0; mt < 2; mt++)
                    mma_tf32(acc[mt][nt][0], acc[mt][nt][1], acc[mt][nt][2], acc[mt][nt][3],
                             a[mt][0], a[mt][1], a[mt][2], a[mt][3], b0, b1);
            }
        }
        __syncthreads();
    }

    #pragma unroll
    for (int mt = 0; mt < 2; mt++) {
        int row = row0 + wm + mt * 16 + quad;
        #pragma unroll
        for (int nt = 0; nt < 4; nt++) {
            int col = col0 + wn + nt * 8 + 2 * c;
            float2 v0 = make_float2(acc[mt][nt][0], acc[mt][nt][1]);
            float2 v1 = make_float2(acc[mt][nt][2], acc[mt][nt][3]);
            *(float2*)&C[(size_t)row * H + col] = v0;
            *(float2*)&C[(size_t)(row + 8) * H + col] = v1;
        }
    }
}

// fused QKV: grid (M/128, 12); y/4 selects W & C, y%4 selects 64-col block
__global__ void __launch_bounds__(256)
qkv_gemm_kernel(const float* __restrict__ Wq,
                const float* __restrict__ Wk,
                const float* __restrict__ Wv) {
    int sel = blockIdx.y >> 2;
    const float* W = (sel == 0) ? Wq : (sel == 1) ? Wk : Wv;
    float* C = (sel == 0) ? g_q : (sel == 1) ? g_k : g_v;
    gemm_mma_body(g_f, W, C, TWO_H, blockIdx.x * 128, (blockIdx.y & 3) * 64);
}

__global__ void __launch_bounds__(256)
wo_gemm_kernel(const float* __restrict__ Wo) {
    gemm_mma_body(g_msg, Wo, g_m, H, blockIdx.x * 128, blockIdx.y * 64);
}

// ---------------- attention (tf32 mma, no-max softmax) ------------------------
// grid (N/128, HEADS, B), 256 threads = 8 warps, warp w -> 16 q rows
__global__ void __launch_bounds__(256)
attn_kernel() {
    __shared__ uint32_t Ks[128][36];   // [j][d] tf32, pad 36 -> QK-frag conflict-free
    __shared__ uint32_t Vs[128][40];   // [j][d] tf32, pad 40 -> PV-frag conflict-free

    int b = blockIdx.z;
    int h = blockIdx.y;
    int q0 = blockIdx.x * 128;
    int t = threadIdx.x;
    int w = t >> 5, lane = t & 31;
    int quad = lane >> 2;      // row within m16 fragment
    int c    = lane & 3;
    int base = lane & ~3;
    int src1 = base | (c >> 1);
    int src2 = base | ((c >> 1) + 2);
    bool odd = (c & 1);

    // load Q fragments (scaled, tf32), rows w*16+quad and +8
    uint32_t qa[4][4];
    {
        const float* qb  = g_q + (size_t)(b * N + q0 + w * 16 + quad) * H + h * DH;
        const float* qb8 = qb + 8 * H;
        #pragma unroll
        for (int ks = 0; ks < 4; ks++) {
            qa[ks][0] = f2tf32(qb [ks * 8 + c]     * SCALE);
            qa[ks][1] = f2tf32(qb8[ks * 8 + c]     * SCALE);
            qa[ks][2] = f2tf32(qb [ks * 8 + c + 4] * SCALE);
            qa[ks][3] = f2tf32(qb8[ks * 8 + c + 4] * SCALE);
        }
    }

    float o[4][4];
    #pragma unroll
    for (int nt = 0; nt < 4; nt++)
        #pragma unroll
        for (int i = 0; i < 4; i++) o[nt][i] = 0.0f;
    float l0 = 0.0f, l1 = 0.0f;

    for (int j0t = 0; j0t < N; j0t += 128) {
        // cooperative K/V tile load (128x32 each)
        #pragma unroll
        for (int it = 0; it < 4; it++) {
            int idx = it * 256 + t;        // 0..1023
            int row = idx >> 3;            // 0..127
            int d4  = (idx & 7) * 4;
            size_t gbase = (size_t)(b * N + j0t + row) * H + h * DH + d4;
            float4 kf = *(const float4*)&g_k[gbase];
            float4 vf = *(const float4*)&g_v[gbase];
            uint4 ku, vu;
            ku.x = f2tf32(kf.x); ku.y = f2tf32(kf.y); ku.z = f2tf32(kf.z); ku.w = f2tf32(kf.w);
            vu.x = f2tf32(vf.x); vu.y = f2tf32(vf.y); vu.z = f2tf32(vf.z); vu.w = f2tf32(vf.w);
            *(uint4*)&Ks[row][d4] = ku;
            *(uint4*)&Vs[row][d4] = vu;
        }
        __syncthreads();

        #pragma unroll 2
        for (int nb = 0; nb < 16; nb++) {
            int j0 = nb * 8;
            // S block: 16 q-rows x 8 j-cols
            float s0 = 0.0f, s1 = 0.0f, s2 = 0.0f, s3 = 0.0f;
            #pragma unroll
            for (int ks = 0; ks < 4; ks++) {
                uint32_t b0 = Ks[j0 + quad][ks * 8 + c];
                uint32_t b1 = Ks[j0 + quad][ks * 8 + c + 4];
                mma_tf32(s0, s1, s2, s3,
                         qa[ks][0], qa[ks][1], qa[ks][2], qa[ks][3], b0, b1);
            }
            // exp (no max shift needed: |s| is O(1))
            float p0 = __expf(s0), p1 = __expf(s1);
            float p2 = __expf(s2), p3 = __expf(s3);
            l0 += p0 + p1;
            l1 += p2 + p3;
            // C-layout -> A-layout via quad shuffles
            uint32_t t0 = f2tf32(p0), t1 = f2tf32(p1);
            uint32_t t2 = f2tf32(p2), t3 = f2tf32(p3);
            uint32_t u0 = __shfl_sync(0xFFFFFFFFu, t0, src1);
            uint32_t u1 = __shfl_sync(0xFFFFFFFFu, t1, src1);
            uint32_t w0 = __shfl_sync(0xFFFFFFFFu, t2, src1);
            uint32_t w1 = __shfl_sync(0xFFFFFFFFu, t3, src1);
            uint32_t v0 = __shfl_sync(0xFFFFFFFFu, t0, src2);
            uint32_t v1 = __shfl_sync(0xFFFFFFFFu, t1, src2);
            uint32_t x0 = __shfl_sync(0xFFFFFFFFu, t2, src2);
            uint32_t x1 = __shfl_sync(0xFFFFFFFFu, t3, src2);
            uint32_t pa0 = odd ? u1 : u0;
            uint32_t pa1 = odd ? w1 : w0;
            uint32_t pa2 = odd ? v1 : v0;
            uint32_t pa3 = odd ? x1 : x0;
            // PV: A = P[16x8], B = V[8x32]
            #pragma unroll
            for (int nt = 0; nt < 4; nt++) {
                uint32_t b0 = Vs[j0 + c][nt * 8 + quad];
                uint32_t b1 = Vs[j0 + c + 4][nt * 8 + quad];
                mma_tf32(o[nt][0], o[nt][1], o[nt][2], o[nt][3],
                         pa0, pa1, pa2, pa3, b0, b1);
            }
        }
        __syncthreads();
    }

    // reduce row sums across quad
    l0 += __shfl_xor_sync(0xFFFFFFFFu, l0, 1);
    l0 += __shfl_xor_sync(0xFFFFFFFFu, l0, 2);
    l1 += __shfl_xor_sync(0xFFFFFFFFu, l1, 1);
    l1 += __shfl_xor_sync(0xFFFFFFFFu, l1, 2);
    float inv0 = 1.0f / l0, inv1 = 1.0f / l1;

    float* ob  = g_msg + (size_t)(b * N + q0 + w * 16 + quad) * H + h * DH;
    float* ob8 = ob + 8 * H;
    #pragma unroll
    for (int nt = 0; nt < 4; nt++) {
        int col = nt * 8 + 2 * c;
        *(float2*)&ob [col] = make_float2(o[nt][0] * inv0, o[nt][1] * inv0);
        *(float2*)&ob8[col] = make_float2(o[nt][2] * inv1, o[nt][3] * inv1);
    }
}

// ---------------- kernel 5: residual + position head -------------------------
__global__ void finish_kernel(const float* __restrict__ x_out,
                              const float* __restrict__ Wp,
                              float* __restrict__ out_x,
                              float* __restrict__ out_p) {
    int warp = threadIdx.x >> 5;
    int lane = threadIdx.x & 31;
    int row = blockIdx.x * 8 + warp;

    const float* mr = g_m + (size_t)row * H;
    float p0 = 0.0f, p1 = 0.0f, p2 = 0.0f;
    #pragma unroll
    for (int c = lane; c < H; c += 32) {
        float mv = mr[c];
        out_x[(size_t)row * H + c] = x_out[(size_t)row * H + c] + mv;
        p0 += mv * Wp[c * DS + 0];
        p1 += mv * Wp[c * DS + 1];
        p2 += mv * Wp[c * DS + 2];
    }
    #pragma unroll
    for (int off = 16; off > 0; off >>= 1) {
        p0 += __shfl_xor_sync(0xFFFFFFFF, p0, off);
        p1 += __shfl_xor_sync(0xFFFFFFFF, p1, off);
        p2 += __shfl_xor_sync(0xFFFFFFFF, p2, off);
    }
    if (lane == 0) {
        out_p[(size_t)row * DS + 0] = p0;
        out_p[(size_t)row * DS + 1] = p1;
        out_p[(size_t)row * DS + 2] = p2;
    }
}

// ---------------- launcher ----------------------------------------------------
extern "C" void kernel_launch(void* const* d_in, const int* in_sizes, int n_in,
                              void* d_out, int out_size) {
    const float* x_source = (const float*)d_in[0];
    const float* x_out    = (const float*)d_in[2];
    const float* gs = (const float*)d_in[4];
    const float* bs = (const float*)d_in[5];
    const float* go = (const float*)d_in[6];
    const float* bo = (const float*)d_in[7];
    const float* Wq = (const float*)d_in[8];
    const float* Wk = (const float*)d_in[9];
    const float* Wv = (const float*)d_in[10];
    const float* Wo = (const float*)d_in[11];
    const float* Wp = (const float*)d_in[12];

    float* out   = (float*)d_out;
    float* out_x = out;
    float* out_p = out + (size_t)M_ROWS * H;

    // 1) layernorm + concat
    ln_concat_kernel<<<M_ROWS, H>>>(x_source, x_out, gs, bs, go, bo);

    // 2) fused QKV projections (tf32 mma)
    dim3 qkv_grid(M_ROWS / 128, 12);
    qkv_gemm_kernel<<<qkv_grid, 256>>>(Wq, Wk, Wv);

    // 3) attention (tf32 mma flash, no-max softmax)
    dim3 agrid(N / 128, HEADS, B);
    attn_kernel<<<agrid, 256>>>();

    // 4) output projection
    dim3 wo_grid(M_ROWS / 128, 4);
    wo_gemm_kernel<<<wo_grid, 256>>>(Wo);

    // 5) residual + position head
    finish_kernel<<<M_ROWS / 8, 256>>>(x_out, Wp, out_x, out_p);
}